// round 13
// baseline (speedup 1.0000x reference)
#include <cuda_runtime.h>
#include <cuda_bf16.h>
#include <stdint.h>
#include <math.h>

#define Dc 256
#define Kc 64
#define TNB 128
#define NTHREADS 256
#define NBUF 2

#if defined(__CUDA_ARCH_FEAT_SM103_ALL) || defined(__CUDA_ARCH_FEAT_SM100_ALL)
#define TC_OK 1
#else
#define TC_OK 0
#endif

// ---- shared memory layout (bytes, from dynamic smem base) ----
#define SM_TMEMPTR 0
#define SM_MB1A    16          // mb1[b] @ +16+8b
#define SM_MB2A    32          // mb2[b] @ +32+8b
#define SM_B       64          // 64 floats bias (pre-scaled by log2e)
#define SM_SCRP    512         // 128 floats partial sums
#define SM_SCRR    1024        // 128 floats rinv
#define SM_WH      2048        // W hi [128 k2][256 d] bf16 SW128 blocked (64KB)
#define SM_XD0     (SM_WH  + 65536)    // 4 subtiles (buf*2+s)*32768: [256 d][64 n]
#define SM_A0      (SM_XD0 + 131072)   // 4 subtiles (buf*2+s)*8192:  [64 k][64 n]
#define SM_TOTAL   (SM_A0  + 32768)    // 231424 B

#define SM_XD(buf, s) (SM_XD0 + (((buf) * 2 + (s)) * 32768))
#define SM_A(buf, s)  (SM_A0  + (((buf) * 2 + (s)) * 8192))

// idesc: kind::f16, dtype=F32, atype=btype=BF16, N=64, M=128
#define IDESC  ((1u<<4) | (1u<<7) | (1u<<10) | (8u<<17) | (8u<<24))
#define IDESC1 (IDESC | (1u<<16))       // + b_major (B is MN-major)

#define SWZ(o) ((o) ^ (((o) >> 3) & 0x70))

// SW128 descriptor: layout=2, version=1, SBO=64, LBO=1 (same for K/MN major;
// the b_major idesc bit carries the transpose).
#define DESC_BASE    0x4000404000010000ULL

#define LOG2E 1.4426950408889634f

__device__ float g_V[Kc * Dc];
__device__ float g_asum[Kc];

// ------------------------- PTX helpers -------------------------
__device__ __forceinline__ uint32_t smem_u32(const void* p) {
    uint32_t a;
    asm("{ .reg .u64 t; cvta.to.shared.u64 t, %1; cvt.u32.u64 %0, t; }" : "=r"(a) : "l"(p));
    return a;
}
__device__ __forceinline__ uint64_t make_desc(uint32_t addr) {
    return DESC_BASE | ((uint64_t)(addr >> 4) & 0x3FFF);
}
#if TC_OK
__device__ __forceinline__ void mma_f16_ss(uint32_t d_tmem, uint64_t a_desc,
                                           uint64_t b_desc, uint32_t idesc, int acc) {
    asm volatile(
        "{\n\t.reg .pred p;\n\tsetp.ne.u32 p, %4, 0;\n\t"
        "tcgen05.mma.cta_group::1.kind::f16 [%0], %1, %2, %3, {%5, %5, %5, %5}, p;\n\t}"
        :: "r"(d_tmem), "l"(a_desc), "l"(b_desc), "r"(idesc), "r"((uint32_t)acc), "r"(0u)
        : "memory");
}
#endif
#define TC_COMMIT(mbar) \
    asm volatile("tcgen05.commit.cta_group::1.mbarrier::arrive::one.shared::cluster.b64 [%0];" \
                 :: "r"(mbar) : "memory")
#define TC_ALLOC(dst, n) \
    asm volatile("tcgen05.alloc.cta_group::1.sync.aligned.shared::cta.b32 [%0], %1;" \
                 :: "r"(dst), "r"(n) : "memory")
#define TC_RELINQ() asm volatile("tcgen05.relinquish_alloc_permit.cta_group::1.sync.aligned;")
#define TC_DEALLOC(base, n) \
    asm volatile("tcgen05.dealloc.cta_group::1.sync.aligned.b32 %0, %1;" :: "r"(base), "r"(n))
#define TC_WAIT_LD() asm volatile("tcgen05.wait::ld.sync.aligned;" ::: "memory")
#define TC_FENCE_AFTER() asm volatile("tcgen05.fence::after_thread_sync;" ::: "memory")
#define TC_FENCE_BEFORE() asm volatile("tcgen05.fence::before_thread_sync;" ::: "memory")
#define FENCE_ASYNC() asm volatile("fence.proxy.async.shared::cta;" ::: "memory")
#define MB_INIT(addr, cnt) \
    asm volatile("mbarrier.init.shared.b64 [%0], %1;" :: "r"(addr), "r"((uint32_t)(cnt)) : "memory")
#define MB_INVAL(addr) asm volatile("mbarrier.inval.shared.b64 [%0];" :: "r"(addr) : "memory")
#define BAR_SYNC(id, cnt) \
    asm volatile("bar.sync %0, %1;" :: "r"(id), "r"(cnt) : "memory")

#define MB_WAIT(mbar, ph) do {                                                  \
    uint32_t _m = (mbar); uint32_t _p = (uint32_t)(ph); uint32_t _done;         \
    asm volatile("{\n\t.reg .pred p;\n\t"                                       \
        "mbarrier.try_wait.parity.acquire.cta.shared::cta.b64 p, [%1], %2;\n\t" \
        "selp.b32 %0, 1, 0, p;\n\t}" : "=r"(_done) : "r"(_m), "r"(_p) : "memory"); \
    if (!_done) {                                                               \
        asm volatile("{\n\t.reg .pred P1;\n\t"                                  \
            "WL_%=:\n\t"                                                        \
            "mbarrier.try_wait.parity.acquire.cta.shared::cta.b64 P1, [%0], %1, 0x989680;\n\t" \
            "@P1 bra.uni WD_%=;\n\t"                                            \
            "bra.uni WL_%=;\n\t"                                                \
            "WD_%=:\n\t}" :: "r"(_m), "r"(_p) : "memory");                      \
    }                                                                           \
} while (0)

#define TC_LD_X32(r, addr)                                                      \
    asm volatile("tcgen05.ld.sync.aligned.32x32b.x32.b32 "                      \
        "{%0, %1, %2, %3, %4, %5, %6, %7, %8, %9, %10, %11, %12, %13, %14, %15, " \
        " %16, %17, %18, %19, %20, %21, %22, %23, %24, %25, %26, %27, %28, %29, %30, %31}, [%32];" \
        : "=r"((r)[0]),  "=r"((r)[1]),  "=r"((r)[2]),  "=r"((r)[3]),            \
          "=r"((r)[4]),  "=r"((r)[5]),  "=r"((r)[6]),  "=r"((r)[7]),            \
          "=r"((r)[8]),  "=r"((r)[9]),  "=r"((r)[10]), "=r"((r)[11]),           \
          "=r"((r)[12]), "=r"((r)[13]), "=r"((r)[14]), "=r"((r)[15]),           \
          "=r"((r)[16]), "=r"((r)[17]), "=r"((r)[18]), "=r"((r)[19]),           \
          "=r"((r)[20]), "=r"((r)[21]), "=r"((r)[22]), "=r"((r)[23]),           \
          "=r"((r)[24]), "=r"((r)[25]), "=r"((r)[26]), "=r"((r)[27]),           \
          "=r"((r)[28]), "=r"((r)[29]), "=r"((r)[30]), "=r"((r)[31])            \
        : "r"(addr))

__device__ __forceinline__ uint32_t b2u(__nv_bfloat162 v) {
    return *(uint32_t*)&v;
}

#if TC_OK
// producer: one wave = 16 float4 per thread = 64 d-rows of the 128-n tile
__device__ __forceinline__ void prod_load(const float* __restrict__ x, int N, int n0,
                                          int tid, int w, float4* v) {
#pragma unroll
    for (int j = 0; j < 16; j++) {
        int i = tid + 128 * (16 * w + j);
        int d = i >> 5, n4 = i & 31;
        v[j] = *(reinterpret_cast<const float4*>(x + (size_t)d * N + n0) + n4);
    }
}
__device__ __forceinline__ void prod_cvst(char* smem, int xb0, int xb1,
                                          int tid, int w, const float4* v) {
#pragma unroll
    for (int j = 0; j < 16; j++) {
        int i = tid + 128 * (16 * w + j);
        int d = i >> 5;
        int n = (i & 31) * 4;
        int base = (n & 64) ? xb1 : xb0;
        __nv_bfloat162 h0 = __float22bfloat162_rn(make_float2(v[j].x, v[j].y));
        __nv_bfloat162 h1 = __float22bfloat162_rn(make_float2(v[j].z, v[j].w));
        uint32_t od = ((uint32_t)(d >> 3) << 10) + ((d & 7) << 7) + ((uint32_t)(n & 63) << 1);
        od = SWZ(od);
        *(uint2*)(smem + base + od) = make_uint2(b2u(h0), b2u(h1));
    }
}
#endif

// ------------------------- kernels -------------------------
__global__ __launch_bounds__(NTHREADS, 1) __cluster_dims__(1, 1, 1)
void netvlad_tc_kernel(const float* __restrict__ x,
                       const float* __restrict__ conv_w,
                       const float* __restrict__ conv_b,
                       int N, int numTiles) {
#if TC_OK
    extern __shared__ char smem[];
    const uint32_t sbase = smem_u32(smem);
    const int tid  = threadIdx.x;
    const int wid  = tid >> 5;
    const int lane = tid & 31;

    // init
    if (tid == 0) {
#pragma unroll
        for (int b = 0; b < NBUF; b++) {
            MB_INIT(sbase + SM_MB1A + 8 * b, 1);
            MB_INIT(sbase + SM_MB2A + 8 * b, 1);
        }
    }
    if (wid == 0) { TC_ALLOC(sbase + SM_TMEMPTR, 512); TC_RELINQ(); }
    if (tid < Kc) *(float*)(smem + SM_B + tid * 4) = conv_b[tid] * LOG2E;
    __syncthreads();
    uint32_t tmem;
    asm volatile("ld.shared.b32 %0, [%1];" : "=r"(tmem) : "r"(sbase + SM_TMEMPTR));

    // stage W hi (pre-scaled by log2e), M=128 (rows 64-127 duplicate rows 0-63).
    for (int i = tid; i < (Kc * Dc) / 4; i += NTHREADS) {
        int k = i >> 6;
        int d0 = (i & 63) * 4;
        float4 w4 = reinterpret_cast<const float4*>(conv_w)[i];
        __nv_bfloat162 h0 = __float22bfloat162_rn(make_float2(w4.x * LOG2E, w4.y * LOG2E));
        __nv_bfloat162 h1 = __float22bfloat162_rn(make_float2(w4.z * LOG2E, w4.w * LOG2E));
        uint32_t o = ((uint32_t)((k >> 3) + ((d0 >> 6) << 4)) << 10) + ((k & 7) << 7) + ((d0 & 63) << 1);
        o = SWZ(o);
        uint2 hv = make_uint2(b2u(h0), b2u(h1));
        *(uint2*)(smem + SM_WH + o) = hv;
        *(uint2*)(smem + SM_WH + o + 8192) = hv;
    }
    FENCE_ASYNC();
    __syncthreads();

    // descriptors
    const uint64_t dWh = make_desc(sbase + SM_WH);
    uint64_t dX[4], dA[4];
#pragma unroll
    for (int q = 0; q < 4; q++) {
        dX[q] = make_desc(sbase + SM_XD0 + q * 32768);
        dA[q] = make_desc(sbase + SM_A0 + q * 8192);
    }
    const float* sBf = (const float*)(smem + SM_B);
    float* scrP = (float*)(smem + SM_SCRP);
    float* scrR = (float*)(smem + SM_SCRR);

    float asum_local = 0.0f;
    int cnt = 0;
    int kk = 0;

    if (tid < 128) {
        // ================= PRODUCER (warps 0-3) =================
        uint32_t ph2 = 0;
        for (int tile = blockIdx.x; tile < numTiles; tile += gridDim.x, cnt++) {
            const int buf = cnt & 1;
            const int n0 = tile * TNB;
            const int xb0 = SM_XD(buf, 0);
            const int xb1 = SM_XD(buf, 1);

            float4 va[16], vb[16];
            prod_load(x, N, n0, tid, 0, va);
            if (cnt >= NBUF) {
                MB_WAIT(sbase + SM_MB2A + 8 * buf, (ph2 >> buf) & 1);
                ph2 ^= (1u << buf);
            }
            prod_load(x, N, n0, tid, 1, vb);
            prod_cvst(smem, xb0, xb1, tid, 0, va);
            prod_load(x, N, n0, tid, 2, va);
            prod_cvst(smem, xb0, xb1, tid, 1, vb);
            prod_load(x, N, n0, tid, 3, vb);
            prod_cvst(smem, xb0, xb1, tid, 2, va);
            prod_cvst(smem, xb0, xb1, tid, 3, vb);
            FENCE_ASYNC();
            BAR_SYNC(1, 128);

            if (tid == 0) {
#pragma unroll
                for (int s = 0; s < 2; s++) {
                    const uint64_t bt = dX[buf * 2 + s];
                    const uint32_t dst = tmem + buf * 128 + s * 64;
#pragma unroll
                    for (int st = 0; st < 16; st++) {
                        uint64_t ao = (uint64_t)(((st >> 2) * 1024) + ((st & 3) * 2));
                        uint64_t bo = (uint64_t)(st * 128);
                        mma_f16_ss(dst, dWh + ao, bt + bo, IDESC1, st != 0);
                    }
                }
                TC_COMMIT(sbase + SM_MB1A + 8 * buf);
            }
        }
    } else {
        // ================= CONSUMER (warps 4-7) =================
        const int cw = wid - 4;                 // 0..3
        kk = ((cw & 1) << 5) + lane;            // k index
        const int np = cw >> 1;                 // subtile / n-pair (64-wide)
        const float bk = sBf[kk];
        uint32_t ph1 = 0;

        for (int tile = blockIdx.x; tile < numTiles; tile += gridDim.x, cnt++) {
            const int buf = cnt & 1;
            const int ab = SM_A(buf, np);

            MB_WAIT(sbase + SM_MB1A + 8 * buf, (ph1 >> buf) & 1);
            ph1 ^= (1u << buf);
            TC_FENCE_AFTER();

            float as = 0.0f;
#pragma unroll
            for (int q = 0; q < 2; q++) {
                uint32_t au[32];
                TC_LD_X32(au, tmem + buf * 128 + np * 64 + q * 32);
                TC_WAIT_LD();
                TC_FENCE_BEFORE();

                float er[32], sr[32];
#pragma unroll
                for (int j = 0; j < 32; j++) {
                    er[j] = exp2f(__uint_as_float(au[j]) + bk);
                    sr[j] = er[j];
                }
                // fold-reduce: lane l ends with sum over 32 k-lanes for col l
#pragma unroll
                for (int off = 16; off > 0; off >>= 1) {
#pragma unroll
                    for (int j = 0; j < 16; j++) {
                        if (j < off) {
                            float x0 = sr[j], x1 = sr[off + j];
                            float mine = (lane & off) ? x1 : x0;
                            float send = (lane & off) ? x0 : x1;
                            float theirs = __shfl_xor_sync(0xffffffffu, send, off);
                            sr[j] = mine + theirs;
                        }
                    }
                }
                scrP[cw * 32 + lane] = sr[0];
                BAR_SYNC(2, 128);
                float tot = sr[0] + scrP[(cw ^ 1) * 32 + lane];
                scrR[np * 64 + q * 32 + lane] = 1.0f / tot;  // dup by k-half pair: same value
                BAR_SYNC(2, 128);

                const float* rsc = scrR + np * 64 + q * 32;
#pragma unroll
                for (int g = 0; g < 4; g++) {
                    uint32_t hv[4];
#pragma unroll
                    for (int r = 0; r < 4; r++) {
                        int j = g * 8 + r * 2;
                        float a0 = er[j] * rsc[j];
                        float a1 = er[j + 1] * rsc[j + 1];
                        __nv_bfloat162 h2 = __float22bfloat162_rn(make_float2(a0, a1));
                        float2 f2 = __bfloat1622float2(h2);
                        as += f2.x + f2.y;   // asum from ROUNDED a (matches GEMM2 operand)
                        hv[r] = b2u(h2);
                    }
                    uint32_t o = ((uint32_t)(kk >> 3) << 10) + ((kk & 7) << 7) + ((uint32_t)(q * 32 + g * 8) << 1);
                    o = SWZ(o);
                    *(uint4*)(smem + ab + o) = make_uint4(hv[0], hv[1], hv[2], hv[3]);
                }
            }
            asum_local += as;
            FENCE_ASYNC();
            BAR_SYNC(2, 128);

            if (tid == 128) {
#pragma unroll
                for (int h = 0; h < 2; h++) {
                    const uint32_t dst = tmem + 256 + 64 * h;
#pragma unroll
                    for (int s = 0; s < 2; s++) {
                        const uint64_t at = dX[buf * 2 + s] + (uint64_t)(h * 1024);
                        const uint64_t bt = dA[buf * 2 + s];
#pragma unroll
                        for (int st = 0; st < 4; st++) {
                            int acc = !(cnt == 0 && s == 0 && st == 0);
                            mma_f16_ss(dst, at + (uint64_t)(st * 2), bt + (uint64_t)(st * 2), IDESC, acc);
                        }
                    }
                }
                TC_COMMIT(sbase + SM_MB2A + 8 * buf);
            }
        }
    }

    __syncthreads();

    // ---- final: wait outstanding GEMM2 per buffer, then flush ----
    if (cnt >= 1) {
        int C0 = (cnt + 1) >> 1;
        int C1 = cnt >> 1;
        if (C0 >= 1) MB_WAIT(sbase + SM_MB2A + 0, (uint32_t)((C0 - 1) & 1));
        if (C1 >= 1) MB_WAIT(sbase + SM_MB2A + 8, (uint32_t)((C1 - 1) & 1));
        TC_FENCE_AFTER();
        uint32_t r[64];
        uint32_t cbase = tmem + 256 + ((tid >= 128) ? 64 : 0);
        TC_LD_X32(r, cbase);
        TC_LD_X32(r + 32, cbase + 32);
        TC_WAIT_LD();
#pragma unroll
        for (int c = 0; c < 64; c++)
            atomicAdd(&g_V[c * Dc + tid], __uint_as_float(r[c]));
        if (tid >= 128) atomicAdd(&g_asum[kk], asum_local);
    }
    __syncthreads();
    if (tid == 0) {
#pragma unroll
        for (int b = 0; b < NBUF; b++) {
            MB_INVAL(sbase + SM_MB1A + 8 * b);
            MB_INVAL(sbase + SM_MB2A + 8 * b);
        }
    }
    __syncthreads();
    if (wid == 0) TC_DEALLOC(tmem, 512);
#else
    // ---------- FFMA fallback (correct on non-a targets; never the fast path) ----------
    extern __shared__ float fsm[];
    float* sW  = fsm;                  // [64][257]
    float* sXT = sW + Kc * 257;        // [64][257]
    float* sA  = sXT + 64 * 257;       // [64][65]
    float* sB  = sA + Kc * 65;         // [64]
    const int tid = threadIdx.x;
    const int ntF = N / 64;
    for (int i = tid; i < (Kc * Dc) / 4; i += NTHREADS) {
        int k = (i * 4) / Dc, d = (i * 4) % Dc;
        float4 w4 = reinterpret_cast<const float4*>(conv_w)[i];
        float* p = &sW[k * 257 + d];
        p[0] = w4.x; p[1] = w4.y; p[2] = w4.z; p[3] = w4.w;
    }
    if (tid < Kc) sB[tid] = conv_b[tid];
    const int tn = tid & 15, tk = tid >> 4;
    const int td = tid & 31, tk2 = tid >> 5;
    float vacc[8][8];
#pragma unroll
    for (int i = 0; i < 8; i++)
#pragma unroll
        for (int j = 0; j < 8; j++) vacc[i][j] = 0.0f;
    float asum_acc = 0.0f;
    for (int tile = blockIdx.x; tile < ntF; tile += gridDim.x) {
        const int n0 = tile * 64;
        __syncthreads();
        for (int i = tid; i < (Dc * 64) / 4; i += NTHREADS) {
            int d = i >> 4, ng = i & 15;
            float4 v = reinterpret_cast<const float4*>(x + (size_t)d * N + n0)[ng];
            int nb = ng * 4;
            sXT[(nb + 0) * 257 + d] = v.x; sXT[(nb + 1) * 257 + d] = v.y;
            sXT[(nb + 2) * 257 + d] = v.z; sXT[(nb + 3) * 257 + d] = v.w;
        }
        __syncthreads();
        float acc[4][4];
#pragma unroll
        for (int i = 0; i < 4; i++)
#pragma unroll
            for (int j = 0; j < 4; j++) acc[i][j] = 0.0f;
#pragma unroll 4
        for (int d = 0; d < Dc; d++) {
            float wv[4], xv[4];
#pragma unroll
            for (int i = 0; i < 4; i++) wv[i] = sW[(tk * 4 + i) * 257 + d];
#pragma unroll
            for (int j = 0; j < 4; j++) xv[j] = sXT[(tn * 4 + j) * 257 + d];
#pragma unroll
            for (int i = 0; i < 4; i++)
#pragma unroll
                for (int j = 0; j < 4; j++) acc[i][j] += wv[i] * xv[j];
        }
#pragma unroll
        for (int i = 0; i < 4; i++) {
            float b = sB[tk * 4 + i];
#pragma unroll
            for (int j = 0; j < 4; j++)
                sA[(tk * 4 + i) * 65 + (tn * 4 + j)] = acc[i][j] + b;
        }
        __syncthreads();
        if (tid < 64) {
            const int n = tid;
            float m = -1e30f;
            for (int k = 0; k < Kc; k++) m = fmaxf(m, sA[k * 65 + n]);
            float s = 0.0f;
            for (int k = 0; k < Kc; k++) {
                float e = __expf(sA[k * 65 + n] - m);
                sA[k * 65 + n] = e; s += e;
            }
            float r = 1.0f / s;
            for (int k = 0; k < Kc; k++) sA[k * 65 + n] *= r;
        }
        __syncthreads();
        if (tid < Kc) {
            float s = 0.0f;
            for (int n = 0; n < 64; n++) s += sA[tid * 65 + n];
            asum_acc += s;
        }
#pragma unroll 2
        for (int n = 0; n < 64; n++) {
            float av[8], xv[8];
#pragma unroll
            for (int i = 0; i < 8; i++) av[i] = sA[(tk2 * 8 + i) * 65 + n];
#pragma unroll
            for (int j = 0; j < 8; j++) xv[j] = sXT[n * 257 + td + 32 * j];
#pragma unroll
            for (int i = 0; i < 8; i++)
#pragma unroll
                for (int j = 0; j < 8; j++) vacc[i][j] += av[i] * xv[j];
        }
    }
#pragma unroll
    for (int i = 0; i < 8; i++)
#pragma unroll
        for (int j = 0; j < 8; j++)
            atomicAdd(&g_V[(tk2 * 8 + i) * Dc + td + 32 * j], vacc[i][j]);
    if (tid < Kc) atomicAdd(&g_asum[tid], asum_acc);
#endif
}

#define SW_STRIDE 257
__global__ void finalize_kernel(const float* __restrict__ c,
                                float* __restrict__ out) {
    extern __shared__ float fsm2[];
    float* sV = fsm2;                     // [64][257]
    float* sAs = sV + Kc * SW_STRIDE;     // [64]
    const int tid = threadIdx.x;          // 256 threads
    if (tid < Kc) {
        sAs[tid] = g_asum[tid];
        g_asum[tid] = 0.0f;               // re-zero for next replay
    }
    __syncthreads();
    const int d = tid;
    float ss = 0.0f;
    for (int k = 0; k < Kc; k++) {
        float v = g_V[k * Dc + d] - c[k * Dc + d] * sAs[k];
        g_V[k * Dc + d] = 0.0f;           // re-zero for next replay
        sV[k * SW_STRIDE + d] = v;
        ss += v * v;
    }
    float r = 1.0f / fmaxf(sqrtf(ss), 1e-12f);
    for (int k = 0; k < Kc; k++) sV[k * SW_STRIDE + d] *= r;
    __syncthreads();
    if (tid < Kc) {
        const int k = tid;
        float rs = 0.0f;
        for (int dd = 0; dd < Dc; dd++) {
            float v = sV[k * SW_STRIDE + dd];
            rs += v * v;
        }
        float rr = 1.0f / fmaxf(sqrtf(rs), 1e-12f);
        for (int dd = 0; dd < Dc; dd++)
            out[k * Dc + dd] = sV[k * SW_STRIDE + dd] * rr;
    }
}

extern "C" void kernel_launch(void* const* d_in, const int* in_sizes, int n_in,
                              void* d_out, int out_size) {
    const float* x      = (const float*)d_in[0];
    const float* c      = (const float*)d_in[1];
    const float* conv_w = (const float*)d_in[2];
    const float* conv_b = (const float*)d_in[3];
    float* out = (float*)d_out;

    const int N = in_sizes[0] / Dc;
    const int numTiles = N / TNB;

    int nsm = 148;
    cudaDeviceGetAttribute(&nsm, cudaDevAttrMultiProcessorCount, 0);

    cudaFuncSetAttribute(netvlad_tc_kernel,
                         cudaFuncAttributeMaxDynamicSharedMemorySize, SM_TOTAL);
    const int fin_smem = (Kc * SW_STRIDE + Kc) * (int)sizeof(float);
    cudaFuncSetAttribute(finalize_kernel,
                         cudaFuncAttributeMaxDynamicSharedMemorySize, fin_smem);

    // g_V / g_asum are zero-initialized statics; finalize_kernel re-zeroes
    // them after reading, so no separate zero pass is needed per replay.
    netvlad_tc_kernel<<<nsm, NTHREADS, SM_TOTAL>>>(x, conv_w, conv_b, N, numTiles);
    finalize_kernel<<<1, 256, fin_smem>>>(c, out);
}

// round 14
// speedup vs baseline: 1.6060x; 1.6060x over previous
#include <cuda_runtime.h>
#include <cuda_bf16.h>
#include <stdint.h>
#include <math.h>

#define Dc 256
#define Kc 64
#define TN 64
#define NTHREADS 256

#if defined(__CUDA_ARCH_FEAT_SM103_ALL) || defined(__CUDA_ARCH_FEAT_SM100_ALL)
#define TC_OK 1
#else
#define TC_OK 0
#endif

// ---- shared memory layout (bytes, from dynamic smem base) ----
#define SM_TMEMPTR 0
#define SM_MB1A    16          // mb1[0]@+16, mb1[1]@+24
#define SM_MB2A    32          // mb2[0]@+32, mb2[1]@+40
#define SM_B       64          // 64 floats bias (pre-scaled by log2e)
#define SM_SCRP    512         // 128 floats partial sums
#define SM_SCRR    1024        // 64 floats rinv
#define SM_WH      2048        // W hi [128 k2][256 d] bf16 SW128 blocked (64KB)
#define SM_XDH0    (SM_WH   + 65536)   // X hi buf0 [256 d][64 n] (32KB)
#define SM_XDH1    (SM_XDH0 + 32768)
#define SM_AH0     (SM_XDH1 + 32768)   // a hi buf0 [64 k][64 n] (8KB)
#define SM_AH1     (SM_AH0  + 8192)
#define SM_TOTAL   (SM_AH1  + 8192)    // 149504 B

// idesc: kind::f16, dtype=F32, atype=btype=BF16, N=64, M=128
#define IDESC  ((1u<<4) | (1u<<7) | (1u<<10) | (8u<<17) | (8u<<24))
#define IDESC1 (IDESC | (1u<<16))       // + b_major (B is MN-major)

#define SWZ(o) ((o) ^ (((o) >> 3) & 0x70))

// SW128 descriptor: layout=2, version=1, SBO=64, LBO=1 (same for K/MN major;
// the b_major idesc bit carries the transpose).
#define DESC_BASE    0x4000404000010000ULL

#define LOG2E 1.4426950408889634f

__device__ float g_V[Kc * Dc];
__device__ float g_asum[Kc];

// ------------------------- PTX helpers -------------------------
__device__ __forceinline__ uint32_t smem_u32(const void* p) {
    uint32_t a;
    asm("{ .reg .u64 t; cvta.to.shared.u64 t, %1; cvt.u32.u64 %0, t; }" : "=r"(a) : "l"(p));
    return a;
}
__device__ __forceinline__ uint64_t make_desc(uint32_t addr) {
    return DESC_BASE | ((uint64_t)(addr >> 4) & 0x3FFF);
}
#if TC_OK
__device__ __forceinline__ void mma_f16_ss(uint32_t d_tmem, uint64_t a_desc,
                                           uint64_t b_desc, uint32_t idesc, int acc) {
    asm volatile(
        "{\n\t.reg .pred p;\n\tsetp.ne.u32 p, %4, 0;\n\t"
        "tcgen05.mma.cta_group::1.kind::f16 [%0], %1, %2, %3, {%5, %5, %5, %5}, p;\n\t}"
        :: "r"(d_tmem), "l"(a_desc), "l"(b_desc), "r"(idesc), "r"((uint32_t)acc), "r"(0u)
        : "memory");
}
#endif
#define TC_COMMIT(mbar) \
    asm volatile("tcgen05.commit.cta_group::1.mbarrier::arrive::one.shared::cluster.b64 [%0];" \
                 :: "r"(mbar) : "memory")
#define TC_ALLOC(dst, n) \
    asm volatile("tcgen05.alloc.cta_group::1.sync.aligned.shared::cta.b32 [%0], %1;" \
                 :: "r"(dst), "r"(n) : "memory")
#define TC_RELINQ() asm volatile("tcgen05.relinquish_alloc_permit.cta_group::1.sync.aligned;")
#define TC_DEALLOC(base, n) \
    asm volatile("tcgen05.dealloc.cta_group::1.sync.aligned.b32 %0, %1;" :: "r"(base), "r"(n))
#define TC_WAIT_LD() asm volatile("tcgen05.wait::ld.sync.aligned;" ::: "memory")
#define TC_FENCE_AFTER() asm volatile("tcgen05.fence::after_thread_sync;" ::: "memory")
#define TC_FENCE_BEFORE() asm volatile("tcgen05.fence::before_thread_sync;" ::: "memory")
#define FENCE_ASYNC() asm volatile("fence.proxy.async.shared::cta;" ::: "memory")
#define MB_INIT(addr, cnt) \
    asm volatile("mbarrier.init.shared.b64 [%0], %1;" :: "r"(addr), "r"((uint32_t)(cnt)) : "memory")
#define MB_INVAL(addr) asm volatile("mbarrier.inval.shared.b64 [%0];" :: "r"(addr) : "memory")
#define BAR_SYNC(id, cnt) \
    asm volatile("bar.sync %0, %1;" :: "r"(id), "r"(cnt) : "memory")

#define MB_WAIT(mbar, ph) do {                                                  \
    uint32_t _m = (mbar); uint32_t _p = (uint32_t)(ph); uint32_t _done;         \
    asm volatile("{\n\t.reg .pred p;\n\t"                                       \
        "mbarrier.try_wait.parity.acquire.cta.shared::cta.b64 p, [%1], %2;\n\t" \
        "selp.b32 %0, 1, 0, p;\n\t}" : "=r"(_done) : "r"(_m), "r"(_p) : "memory"); \
    if (!_done) {                                                               \
        asm volatile("{\n\t.reg .pred P1;\n\t"                                  \
            "WL_%=:\n\t"                                                        \
            "mbarrier.try_wait.parity.acquire.cta.shared::cta.b64 P1, [%0], %1, 0x989680;\n\t" \
            "@P1 bra.uni WD_%=;\n\t"                                            \
            "bra.uni WL_%=;\n\t"                                                \
            "WD_%=:\n\t}" :: "r"(_m), "r"(_p) : "memory");                      \
    }                                                                           \
} while (0)

#define TC_LD_X32(r, addr)                                                      \
    asm volatile("tcgen05.ld.sync.aligned.32x32b.x32.b32 "                      \
        "{%0, %1, %2, %3, %4, %5, %6, %7, %8, %9, %10, %11, %12, %13, %14, %15, " \
        " %16, %17, %18, %19, %20, %21, %22, %23, %24, %25, %26, %27, %28, %29, %30, %31}, [%32];" \
        : "=r"((r)[0]),  "=r"((r)[1]),  "=r"((r)[2]),  "=r"((r)[3]),            \
          "=r"((r)[4]),  "=r"((r)[5]),  "=r"((r)[6]),  "=r"((r)[7]),            \
          "=r"((r)[8]),  "=r"((r)[9]),  "=r"((r)[10]), "=r"((r)[11]),           \
          "=r"((r)[12]), "=r"((r)[13]), "=r"((r)[14]), "=r"((r)[15]),           \
          "=r"((r)[16]), "=r"((r)[17]), "=r"((r)[18]), "=r"((r)[19]),           \
          "=r"((r)[20]), "=r"((r)[21]), "=r"((r)[22]), "=r"((r)[23]),           \
          "=r"((r)[24]), "=r"((r)[25]), "=r"((r)[26]), "=r"((r)[27]),           \
          "=r"((r)[28]), "=r"((r)[29]), "=r"((r)[30]), "=r"((r)[31])            \
        : "r"(addr))

__device__ __forceinline__ uint32_t b2u(__nv_bfloat162 v) {
    return *(uint32_t*)&v;
}

// ------------------------- main kernel -------------------------
__global__ __launch_bounds__(NTHREADS, 1) __cluster_dims__(1, 1, 1)
void netvlad_tc_kernel(const float* __restrict__ x,
                       const float* __restrict__ conv_w,
                       const float* __restrict__ conv_b,
                       int N, int numTiles) {
#if TC_OK
    extern __shared__ char smem[];
    const uint32_t sbase = smem_u32(smem);
    const int tid  = threadIdx.x;
    const int wid  = tid >> 5;
    const int lane = tid & 31;

    // init
    if (tid == 0) {
        MB_INIT(sbase + SM_MB1A + 0, 1); MB_INIT(sbase + SM_MB1A + 8, 1);
        MB_INIT(sbase + SM_MB2A + 0, 1); MB_INIT(sbase + SM_MB2A + 8, 1);
    }
    if (wid == 0) { TC_ALLOC(sbase + SM_TMEMPTR, 256); TC_RELINQ(); }
    if (tid < Kc) *(float*)(smem + SM_B + tid * 4) = conv_b[tid] * LOG2E;
    __syncthreads();
    uint32_t tmem;
    asm volatile("ld.shared.b32 %0, [%1];" : "=r"(tmem) : "r"(sbase + SM_TMEMPTR));

    // stage W hi (pre-scaled by log2e), M=128 (rows 64-127 duplicate rows 0-63).
    for (int i = tid; i < (Kc * Dc) / 4; i += NTHREADS) {
        int k = i >> 6;
        int d0 = (i & 63) * 4;
        float4 w4 = reinterpret_cast<const float4*>(conv_w)[i];
        __nv_bfloat162 h0 = __float22bfloat162_rn(make_float2(w4.x * LOG2E, w4.y * LOG2E));
        __nv_bfloat162 h1 = __float22bfloat162_rn(make_float2(w4.z * LOG2E, w4.w * LOG2E));
        uint32_t o = ((uint32_t)((k >> 3) + ((d0 >> 6) << 4)) << 10) + ((k & 7) << 7) + ((d0 & 63) << 1);
        o = SWZ(o);
        uint2 hv = make_uint2(b2u(h0), b2u(h1));
        *(uint2*)(smem + SM_WH + o) = hv;
        *(uint2*)(smem + SM_WH + o + 8192) = hv;
    }
    FENCE_ASYNC();
    __syncthreads();

    // descriptors
    const uint64_t dWh = make_desc(sbase + SM_WH);
    const uint64_t dX0 = make_desc(sbase + SM_XDH0);
    const uint64_t dX1 = make_desc(sbase + SM_XDH1);
    const uint64_t dA0 = make_desc(sbase + SM_AH0);
    const uint64_t dA1 = make_desc(sbase + SM_AH1);
    const float* sBf = (const float*)(smem + SM_B);
    float* scrP = (float*)(smem + SM_SCRP);
    float* scrR = (float*)(smem + SM_SCRR);

    float asum_local = 0.0f;
    int cnt = 0;
    int kk = 0;

    if (tid < 128) {
        // ================= PRODUCER (warps 0-3) =================
        uint32_t ph2 = 0;
        for (int tile = blockIdx.x; tile < numTiles; tile += gridDim.x, cnt++) {
            const int buf = cnt & 1;
            const int n0 = tile * TN;
            const int xb = buf ? SM_XDH1 : SM_XDH0;

            // prefetch first half before the wait (hide DRAM latency)
            float4 v[16];
#pragma unroll
            for (int j = 0; j < 16; j++) {
                int i = tid + 128 * j;
                v[j] = *(reinterpret_cast<const float4*>(x + (size_t)(i >> 4) * N + n0) + (i & 15));
            }

            if (cnt >= 2) {
                MB_WAIT(sbase + SM_MB2A + 8 * buf, (ph2 >> buf) & 1);
                ph2 ^= (1u << buf);
            }

            float4 v2[16];
#pragma unroll
            for (int j = 0; j < 16; j++) {
                int i = tid + 128 * (16 + j);
                v2[j] = *(reinterpret_cast<const float4*>(x + (size_t)(i >> 4) * N + n0) + (i & 15));
            }

#pragma unroll
            for (int j = 0; j < 16; j++) {
                int i = tid + 128 * j;
                int d = i >> 4, n = (i & 15) * 4;
                __nv_bfloat162 h0 = __float22bfloat162_rn(make_float2(v[j].x, v[j].y));
                __nv_bfloat162 h1 = __float22bfloat162_rn(make_float2(v[j].z, v[j].w));
                uint32_t od = ((uint32_t)(d >> 3) << 10) + ((d & 7) << 7) + (n << 1);
                od = SWZ(od);
                *(uint2*)(smem + xb + od) = make_uint2(b2u(h0), b2u(h1));
            }
#pragma unroll
            for (int j = 0; j < 16; j++) {
                int i = tid + 128 * (16 + j);
                int d = i >> 4, n = (i & 15) * 4;
                __nv_bfloat162 h0 = __float22bfloat162_rn(make_float2(v2[j].x, v2[j].y));
                __nv_bfloat162 h1 = __float22bfloat162_rn(make_float2(v2[j].z, v2[j].w));
                uint32_t od = ((uint32_t)(d >> 3) << 10) + ((d & 7) << 7) + (n << 1);
                od = SWZ(od);
                *(uint2*)(smem + xb + od) = make_uint2(b2u(h0), b2u(h1));
            }
            FENCE_ASYNC();
            BAR_SYNC(1, 128);

            if (tid == 0) {
                const uint64_t bt = buf ? dX1 : dX0;
#pragma unroll
                for (int s = 0; s < 16; s++) {
                    uint64_t ao = (uint64_t)(((s >> 2) * 1024) + ((s & 3) * 2));
                    uint64_t bo = (uint64_t)(s * 128);
                    mma_f16_ss(tmem + buf * 64, dWh + ao, bt + bo, IDESC1, s != 0);
                }
                TC_COMMIT(sbase + SM_MB1A + 8 * buf);
            }
        }
    } else {
        // ================= CONSUMER (warps 4-7) =================
        const int cw = wid - 4;                 // 0..3
        kk = ((cw & 1) << 5) + lane;            // k index
        const int nh = cw >> 1;                 // n-half
        const float bk = sBf[kk];
        uint32_t ph1 = 0;

        for (int tile = blockIdx.x; tile < numTiles; tile += gridDim.x, cnt++) {
            const int buf = cnt & 1;
            const int ab = buf ? SM_AH1 : SM_AH0;

            MB_WAIT(sbase + SM_MB1A + 8 * buf, (ph1 >> buf) & 1);
            ph1 ^= (1u << buf);
            TC_FENCE_AFTER();
            uint32_t au[32];
            TC_LD_X32(au, tmem + buf * 64 + nh * 32);
            TC_WAIT_LD();
            TC_FENCE_BEFORE();

            float er[32], sr[32];
#pragma unroll
            for (int j = 0; j < 32; j++) {
                er[j] = exp2f(__uint_as_float(au[j]) + bk);
                sr[j] = er[j];
            }
            // fold-reduce: lane l ends with sum over 32 k-lanes for n = nh*32+l
#pragma unroll
            for (int off = 16; off > 0; off >>= 1) {
#pragma unroll
                for (int j = 0; j < 16; j++) {
                    if (j < off) {
                        float x0 = sr[j], x1 = sr[off + j];
                        float mine = (lane & off) ? x1 : x0;
                        float send = (lane & off) ? x0 : x1;
                        float theirs = __shfl_xor_sync(0xffffffffu, send, off);
                        sr[j] = mine + theirs;
                    }
                }
            }
            scrP[cw * 32 + lane] = sr[0];
            BAR_SYNC(2, 128);
            float tot = sr[0] + scrP[(cw ^ 1) * 32 + lane];
            scrR[nh * 32 + lane] = 1.0f / tot;
            BAR_SYNC(2, 128);

            const float* rsc = scrR + nh * 32;
            float as = 0.0f;
#pragma unroll
            for (int q = 0; q < 4; q++) {
                uint32_t hv[4];
#pragma unroll
                for (int r = 0; r < 4; r++) {
                    int j = q * 8 + r * 2;
                    float a0 = er[j] * rsc[j];
                    float a1 = er[j + 1] * rsc[j + 1];
                    __nv_bfloat162 h2 = __float22bfloat162_rn(make_float2(a0, a1));
                    float2 f2 = __bfloat1622float2(h2);
                    as += f2.x + f2.y;   // asum from ROUNDED a (matches GEMM2 operand)
                    hv[r] = b2u(h2);
                }
                uint32_t o = ((uint32_t)(kk >> 3) << 10) + ((kk & 7) << 7) + ((uint32_t)(nh * 32 + q * 8) << 1);
                o = SWZ(o);
                *(uint4*)(smem + ab + o) = make_uint4(hv[0], hv[1], hv[2], hv[3]);
            }
            asum_local += as;
            FENCE_ASYNC();
            BAR_SYNC(2, 128);

            if (tid == 128) {
                const uint64_t dXp = buf ? dX1 : dX0;
                const uint64_t dAp = buf ? dA1 : dA0;
#pragma unroll
                for (int h = 0; h < 2; h++)
#pragma unroll
                    for (int s = 0; s < 4; s++) {
                        int acc = !(cnt == 0 && s == 0);
                        mma_f16_ss(tmem + 128 + 64 * h,
                                   dXp + (uint64_t)(h * 1024 + s * 2),
                                   dAp + (uint64_t)(s * 2), IDESC, acc);
                    }
                TC_COMMIT(sbase + SM_MB2A + 8 * buf);
            }
        }
    }

    __syncthreads();

    // ---- final: wait outstanding GEMM2 per buffer, then flush ----
    if (cnt >= 1) {
        int C0 = (cnt + 1) >> 1;
        int C1 = cnt >> 1;
        if (C0 >= 1) MB_WAIT(sbase + SM_MB2A + 0, (uint32_t)((C0 - 1) & 1));
        if (C1 >= 1) MB_WAIT(sbase + SM_MB2A + 8, (uint32_t)((C1 - 1) & 1));
        TC_FENCE_AFTER();
        uint32_t r[64];
        uint32_t cbase = tmem + 128 + ((tid >= 128) ? 64 : 0);
        TC_LD_X32(r, cbase);
        TC_LD_X32(r + 32, cbase + 32);
        TC_WAIT_LD();
#pragma unroll
        for (int c = 0; c < 64; c++)
            atomicAdd(&g_V[c * Dc + tid], __uint_as_float(r[c]));
        if (tid >= 128) atomicAdd(&g_asum[kk], asum_local);
    }
    __syncthreads();
    if (tid == 0) {
        MB_INVAL(sbase + SM_MB1A + 0); MB_INVAL(sbase + SM_MB1A + 8);
        MB_INVAL(sbase + SM_MB2A + 0); MB_INVAL(sbase + SM_MB2A + 8);
    }
    __syncthreads();
    if (wid == 0) TC_DEALLOC(tmem, 256);
#else
    // ---------- FFMA fallback (correct on non-a targets; never the fast path) ----------
    extern __shared__ float fsm[];
    float* sW  = fsm;                  // [64][257]
    float* sXT = sW + Kc * 257;        // [64][257]
    float* sA  = sXT + TN * 257;       // [64][65]
    float* sB  = sA + Kc * 65;         // [64]
    const int tid = threadIdx.x;
    for (int i = tid; i < (Kc * Dc) / 4; i += NTHREADS) {
        int k = (i * 4) / Dc, d = (i * 4) % Dc;
        float4 w4 = reinterpret_cast<const float4*>(conv_w)[i];
        float* p = &sW[k * 257 + d];
        p[0] = w4.x; p[1] = w4.y; p[2] = w4.z; p[3] = w4.w;
    }
    if (tid < Kc) sB[tid] = conv_b[tid];
    const int tn = tid & 15, tk = tid >> 4;
    const int td = tid & 31, tk2 = tid >> 5;
    float vacc[8][8];
#pragma unroll
    for (int i = 0; i < 8; i++)
#pragma unroll
        for (int j = 0; j < 8; j++) vacc[i][j] = 0.0f;
    float asum_acc = 0.0f;
    for (int tile = blockIdx.x; tile < numTiles; tile += gridDim.x) {
        const int n0 = tile * TN;
        __syncthreads();
        for (int i = tid; i < (Dc * TN) / 4; i += NTHREADS) {
            int d = i >> 4, ng = i & 15;
            float4 v = reinterpret_cast<const float4*>(x + (size_t)d * N + n0)[ng];
            int nb = ng * 4;
            sXT[(nb + 0) * 257 + d] = v.x; sXT[(nb + 1) * 257 + d] = v.y;
            sXT[(nb + 2) * 257 + d] = v.z; sXT[(nb + 3) * 257 + d] = v.w;
        }
        __syncthreads();
        float acc[4][4];
#pragma unroll
        for (int i = 0; i < 4; i++)
#pragma unroll
            for (int j = 0; j < 4; j++) acc[i][j] = 0.0f;
#pragma unroll 4
        for (int d = 0; d < Dc; d++) {
            float wv[4], xv[4];
#pragma unroll
            for (int i = 0; i < 4; i++) wv[i] = sW[(tk * 4 + i) * 257 + d];
#pragma unroll
            for (int j = 0; j < 4; j++) xv[j] = sXT[(tn * 4 + j) * 257 + d];
#pragma unroll
            for (int i = 0; i < 4; i++)
#pragma unroll
                for (int j = 0; j < 4; j++) acc[i][j] += wv[i] * xv[j];
        }
#pragma unroll
        for (int i = 0; i < 4; i++) {
            float b = sB[tk * 4 + i];
#pragma unroll
            for (int j = 0; j < 4; j++)
                sA[(tk * 4 + i) * 65 + (tn * 4 + j)] = acc[i][j] + b;
        }
        __syncthreads();
        if (tid < TN) {
            const int n = tid;
            float m = -1e30f;
            for (int k = 0; k < Kc; k++) m = fmaxf(m, sA[k * 65 + n]);
            float s = 0.0f;
            for (int k = 0; k < Kc; k++) {
                float e = __expf(sA[k * 65 + n] - m);
                sA[k * 65 + n] = e; s += e;
            }
            float r = 1.0f / s;
            for (int k = 0; k < Kc; k++) sA[k * 65 + n] *= r;
        }
        __syncthreads();
        if (tid < Kc) {
            float s = 0.0f;
            for (int n = 0; n < TN; n++) s += sA[tid * 65 + n];
            asum_acc += s;
        }
#pragma unroll 2
        for (int n = 0; n < TN; n++) {
            float av[8], xv[8];
#pragma unroll
            for (int i = 0; i < 8; i++) av[i] = sA[(tk2 * 8 + i) * 65 + n];
#pragma unroll
            for (int j = 0; j < 8; j++) xv[j] = sXT[n * 257 + td + 32 * j];
#pragma unroll
            for (int i = 0; i < 8; i++)
#pragma unroll
                for (int j = 0; j < 8; j++) vacc[i][j] += av[i] * xv[j];
        }
    }
#pragma unroll
    for (int i = 0; i < 8; i++)
#pragma unroll
        for (int j = 0; j < 8; j++)
            atomicAdd(&g_V[(tk2 * 8 + i) * Dc + td + 32 * j], vacc[i][j]);
    if (tid < Kc) atomicAdd(&g_asum[tid], asum_acc);
#endif
}

// ------------------------- finalize (1024 threads, MLP-friendly) -------------------------
// dyn smem floats: sV[64][257], sAs[64], scr[1024], rinv[256], rr[64]
#define FSV   0
#define FAS   (Kc * 257)
#define FSCR  (FAS + 64)
#define FRINV (FSCR + 1024)
#define FRR   (FRINV + 256)
#define FTOT  (FRR + 64)

__global__ __launch_bounds__(1024) void finalize_kernel(const float* __restrict__ c,
                                                        float* __restrict__ out) {
    extern __shared__ float fs[];
    const int tid = threadIdx.x;
    const int g = tid >> 8;     // k-group 0..3
    const int d = tid & 255;    // column

    if (tid < Kc) {
        fs[FAS + tid] = g_asum[tid];
        g_asum[tid] = 0.0f;     // re-zero for next replay
    }
    __syncthreads();

    // Phase A: V = g_V - c*asum ; column (axis-0) sum of squares, 4-way split over k
    float part = 0.0f;
#pragma unroll
    for (int j = 0; j < 16; j++) {
        int k = g * 16 + j;
        float v = g_V[k * Dc + d] - c[k * Dc + d] * fs[FAS + k];
        g_V[k * Dc + d] = 0.0f; // re-zero for next replay
        fs[FSV + k * 257 + d] = v;
        part += v * v;
    }
    fs[FSCR + tid] = part;
    __syncthreads();
    if (tid < 256) {
        float ss = fs[FSCR + tid] + fs[FSCR + 256 + tid] + fs[FSCR + 512 + tid] + fs[FSCR + 768 + tid];
        fs[FRINV + tid] = 1.0f / fmaxf(sqrtf(ss), 1e-12f);
    }
    __syncthreads();

    // Phase B: row (axis-1) L2 of the column-normalized V, 4-way split over d
    if (tid < 256) {
        int k = tid & 63, q = tid >> 6;
        float part2 = 0.0f;
#pragma unroll
        for (int j = 0; j < 64; j++) {
            int dd = q * 64 + j;
            float t = fs[FSV + k * 257 + dd] * fs[FRINV + dd];
            part2 += t * t;
        }
        fs[FSCR + q * 64 + k] = part2;
    }
    __syncthreads();
    if (tid < 64) {
        float rs = fs[FSCR + tid] + fs[FSCR + 64 + tid] + fs[FSCR + 128 + tid] + fs[FSCR + 192 + tid];
        fs[FRR + tid] = 1.0f / fmaxf(sqrtf(rs), 1e-12f);
    }
    __syncthreads();

    // writeback
#pragma unroll
    for (int j = 0; j < 16; j++) {
        int k = g * 16 + j;
        out[k * Dc + d] = fs[FSV + k * 257 + d] * fs[FRINV + d] * fs[FRR + k];
    }
}

extern "C" void kernel_launch(void* const* d_in, const int* in_sizes, int n_in,
                              void* d_out, int out_size) {
    const float* x      = (const float*)d_in[0];
    const float* c      = (const float*)d_in[1];
    const float* conv_w = (const float*)d_in[2];
    const float* conv_b = (const float*)d_in[3];
    float* out = (float*)d_out;

    const int N = in_sizes[0] / Dc;
    const int numTiles = N / TN;

    int nsm = 148;
    cudaDeviceGetAttribute(&nsm, cudaDevAttrMultiProcessorCount, 0);

    cudaFuncSetAttribute(netvlad_tc_kernel,
                         cudaFuncAttributeMaxDynamicSharedMemorySize, SM_TOTAL);
    const int fin_smem = FTOT * (int)sizeof(float);
    cudaFuncSetAttribute(finalize_kernel,
                         cudaFuncAttributeMaxDynamicSharedMemorySize, fin_smem);

    // g_V / g_asum are zero-initialized statics; finalize_kernel re-zeroes
    // them after reading, so no separate zero pass is needed per replay.
    netvlad_tc_kernel<<<nsm, NTHREADS, SM_TOTAL>>>(x, conv_w, conv_b, N, numTiles);
    finalize_kernel<<<1, 1024, fin_smem>>>(c, out);
}